// round 12
// baseline (speedup 1.0000x reference)
#include <cuda_runtime.h>
#include <cuda_bf16.h>
#include <cstdint>

// ConjunctionLayer via mma.sync tensor cores (portable PTX, no tcgen05):
// s[b,j] = sum_k ln(1 + a_k w_k), a = x-1 in (-1,0], w in [0,0.5)
//        = sum_{n=1..6} c_n dot(a^n, w^n), c_n = (-1)^(n+1)/n  (Mercator)
// Term 1 split hi/lo on both sides -> 8 bf16 GEMM slots, K' = 8 x 512.
// out = -1/(s-1). Slot-major K, KSPLIT=4 (2 slots/CTA sharing x powers).
// A built on the fly (bf16 powers -> smem), B precomputed chunk images.
// m16n8k16 bf16 mma + ldmatrix.x4; ticket-counter finalize (graph-safe).

#define Bdim 4096
#define Ddim 512
#define Ndim 128

#define MT     128
#define NMT    (Bdim / MT)      // 32 m-tiles
#define KSPLIT 4
#define NKC    16               // 32-k chunks per slot
#define NCH    32               // chunks per CTA: (kc, s) pairs
#define AROW   80               // smem row stride bytes (32 bf16 data + pad)
#define IMGB   (128 * AROW)     // 10240 B per chunk image

__device__ uint4 g_bmat[128 * IMGB / 16];          // 1.31MB B slot images
__device__ float g_partial[KSPLIT][Bdim * Ndim];   // 8MB partial sums
__device__ int   g_cnt[NMT];                       // tickets (self-reset)

__device__ __forceinline__ uint32_t pack_bf16x2(float lo, float hi) {
    uint32_t d;
    asm("cvt.rn.bf16x2.f32 %0, %1, %2;" : "=r"(d) : "f"(hi), "f"(lo));
    return d;
}
__device__ __forceinline__ void cp16(uint32_t dst, const void* src) {
    asm volatile("cp.async.cg.shared.global [%0], [%1], 16;" :: "r"(dst), "l"(src));
}
__device__ __forceinline__ void ldsm4(uint32_t* r, uint32_t addr) {
    asm volatile("ldmatrix.sync.aligned.m8n8.x4.shared.b16 {%0,%1,%2,%3}, [%4];"
                 : "=r"(r[0]), "=r"(r[1]), "=r"(r[2]), "=r"(r[3]) : "r"(addr));
}
__device__ __forceinline__ void mma16816(float* c, const uint32_t* A,
                                         uint32_t b0, uint32_t b1) {
    asm volatile(
        "mma.sync.aligned.m16n8k16.row.col.f32.bf16.bf16.f32 "
        "{%0,%1,%2,%3}, {%4,%5,%6,%7}, {%8,%9}, {%0,%1,%2,%3};"
        : "+f"(c[0]), "+f"(c[1]), "+f"(c[2]), "+f"(c[3])
        : "r"(A[0]), "r"(A[1]), "r"(A[2]), "r"(A[3]), "r"(b0), "r"(b1));
}

// ---- B slot images: img = t*NKC + kc; rows j=0..127, 32 bf16 (+pad) ----
__global__ void prep_w(const float* __restrict__ W) {
    int img = blockIdx.x;
    int t = img >> 4, kc = img & 15;
    int r = threadIdx.x >> 1, half = threadIdx.x & 1;
    const float* wp = &W[r * Ddim + kc * 32 + half * 16];
    uint32_t pk[8];
#pragma unroll
    for (int i = 0; i < 8; i++) {
        float w0 = wp[2 * i], w1 = wp[2 * i + 1];
        float v0, v1;
        switch (t) {
            case 0: case 2: v0 = w0; v1 = w1; break;
            case 1:
                v0 = w0 - __bfloat162float(__float2bfloat16(w0));
                v1 = w1 - __bfloat162float(__float2bfloat16(w1));
                break;
            case 3: v0 = -0.5f * w0 * w0; v1 = -0.5f * w1 * w1; break;
            case 4: v0 = w0 * w0 * w0 * (1.0f / 3.0f);
                    v1 = w1 * w1 * w1 * (1.0f / 3.0f); break;
            case 5: { float a2 = w0 * w0, b2 = w1 * w1;
                      v0 = -0.25f * a2 * a2; v1 = -0.25f * b2 * b2; } break;
            case 6: { float a2 = w0 * w0, b2 = w1 * w1;
                      v0 = a2 * a2 * w0 * 0.2f; v1 = b2 * b2 * w1 * 0.2f; } break;
            default: { float a2 = w0 * w0, b2 = w1 * w1;
                       v0 = -a2 * a2 * a2 * (1.0f / 6.0f);
                       v1 = -b2 * b2 * b2 * (1.0f / 6.0f); } break;
        }
        pk[i] = pack_bf16x2(v0, v1);
    }
    char* dst = (char*)g_bmat + img * IMGB + r * AROW + half * 32;
    ((uint4*)dst)[0] = make_uint4(pk[0], pk[1], pk[2], pk[3]);
    ((uint4*)(dst + 16))[0] = make_uint4(pk[4], pk[5], pk[6], pk[7]);
}

// ---- main fused GEMM ----
__global__ __launch_bounds__(256)
void conj_mma(const float* __restrict__ x, float* __restrict__ out) {
    __shared__ __align__(128) char smem[4 * IMGB];   // A0 A1 B0 B1
    __shared__ int s_last;

    const int tid = threadIdx.x, wid = tid >> 5, lane = tid & 31;
    const int mtile = blockIdx.x >> 2, ks = blockIdx.x & 3;
    const int b0 = mtile * MT;
    const int wm = wid >> 1, wn = wid & 1;    // warp tile: rows wm*32, cols wn*64

    const uint32_t sb = (uint32_t)__cvta_generic_to_shared(smem);
    const uint32_t sA0 = sb, sB0 = sb + 2 * IMGB;

    float acc[2][8][4];
#pragma unroll
    for (int mt = 0; mt < 2; mt++)
#pragma unroll
        for (int nt = 0; nt < 8; nt++)
#pragma unroll
            for (int c = 0; c < 4; c++) acc[mt][nt][c] = 0.0f;

    // staging map: thread = (row r, k-half)
    const int r = tid >> 1, half = tid & 1;
    const float* xrow = &x[(b0 + r) * Ddim + half * 16];
    const uint32_t aSts = sA0 + r * AROW + half * 32;

    // ldmatrix lane-address bases
    const uint32_t aLd = sA0 + (wm * 32 + (lane & 15)) * AROW + (lane & 16);
    const uint32_t bLd = sB0 + (wn * 64 + (lane & 7) + ((lane >> 1) & 8)) * AROW
                             + ((lane & 8) << 1);

    float a[16], aN[16], pw[16];

#define LDG_A(KC, D)                                                          \
    do {                                                                      \
        _Pragma("unroll")                                                     \
        for (int q = 0; q < 4; q++) {                                         \
            float4 v = *(const float4*)&xrow[(KC) * 32 + q * 4];              \
            (D)[4*q+0] = v.x - 1.0f; (D)[4*q+1] = v.y - 1.0f;                 \
            (D)[4*q+2] = v.z - 1.0f; (D)[4*q+3] = v.w - 1.0f;                 \
        }                                                                     \
    } while (0)

#define STAGE_A(S, P)                                                         \
    do {                                                                      \
        float st[16];                                                         \
        if (ks == 0) {                                                        \
            _Pragma("unroll") for (int i = 0; i < 16; i++) st[i] = a[i];      \
        } else if (ks == 1) {                                                 \
            if ((S) == 0) {                                                   \
                _Pragma("unroll") for (int i = 0; i < 16; i++)                \
                    st[i] = a[i] - __bfloat162float(__float2bfloat16(a[i]));  \
            } else {                                                          \
                _Pragma("unroll") for (int i = 0; i < 16; i++)                \
                    st[i] = a[i] * a[i];                                      \
            }                                                                 \
        } else if (ks == 2) {                                                 \
            if ((S) == 0) {                                                   \
                _Pragma("unroll") for (int i = 0; i < 16; i++)                \
                    { pw[i] = a[i] * a[i] * a[i]; st[i] = pw[i]; }            \
            } else {                                                          \
                _Pragma("unroll") for (int i = 0; i < 16; i++)                \
                    { pw[i] *= a[i]; st[i] = pw[i]; }                         \
            }                                                                 \
        } else {                                                              \
            if ((S) == 0) {                                                   \
                _Pragma("unroll") for (int i = 0; i < 16; i++)                \
                    { float t2 = a[i] * a[i]; pw[i] = t2 * t2 * a[i];         \
                      st[i] = pw[i]; }                                        \
            } else {                                                          \
                _Pragma("unroll") for (int i = 0; i < 16; i++)                \
                    { pw[i] *= a[i]; st[i] = pw[i]; }                         \
            }                                                                 \
        }                                                                     \
        uint32_t pk[8];                                                       \
        _Pragma("unroll") for (int i = 0; i < 8; i++)                         \
            pk[i] = pack_bf16x2(st[2*i], st[2*i+1]);                          \
        uint32_t ad = aSts + (P) * IMGB;                                      \
        asm volatile("st.shared.v4.b32 [%0], {%1,%2,%3,%4};"                  \
                     :: "r"(ad), "r"(pk[0]), "r"(pk[1]), "r"(pk[2]), "r"(pk[3])); \
        asm volatile("st.shared.v4.b32 [%0], {%1,%2,%3,%4};"                  \
                     :: "r"(ad + 16), "r"(pk[4]), "r"(pk[5]), "r"(pk[6]), "r"(pk[7])); \
    } while (0)

#define STAGE_B(CH, P)                                                        \
    do {                                                                      \
        int img = (ks * 2 + ((CH) & 1)) * NKC + ((CH) >> 1);                  \
        const char* src = (const char*)g_bmat + img * IMGB;                   \
        _Pragma("unroll")                                                     \
        for (int q = 0; q < 3; q++) {                                         \
            int idx = tid + q * 256;                                          \
            if (idx < IMGB / 16)                                              \
                cp16(sB0 + (P) * IMGB + idx * 16, src + idx * 16);            \
        }                                                                     \
        asm volatile("cp.async.commit_group;");                               \
    } while (0)

    // prologue
    LDG_A(0, a);
    STAGE_A(0, 0);
    STAGE_B(0, 0);
    LDG_A(1, aN);

    for (int ch = 0; ch < NCH; ch++) {
        const int p = ch & 1;
        asm volatile("cp.async.wait_group 0;");
        __syncthreads();    // buf p ready; buf p^1 fully consumed

        if (ch + 1 < NCH) {
            const int s1 = (ch + 1) & 1;
            if (s1 == 0) {
#pragma unroll
                for (int i = 0; i < 16; i++) a[i] = aN[i];
            }
            STAGE_A(s1, p ^ 1);
            if (s1 == 0) {
                int kcn = ((ch + 1) >> 1) + 1;
                if (kcn < NKC) LDG_A(kcn, aN);
            }
            STAGE_B(ch + 1, p ^ 1);
        }

        // compute chunk from buf p: two k16 steps
#pragma unroll
        for (int ksx = 0; ksx < 2; ksx++) {
            uint32_t af[2][4], bf_[4][4];
#pragma unroll
            for (int mt = 0; mt < 2; mt++)
                ldsm4(af[mt], aLd + p * IMGB + mt * (16 * AROW) + ksx * 32);
#pragma unroll
            for (int q = 0; q < 4; q++)
                ldsm4(bf_[q], bLd + p * IMGB + q * (16 * AROW) + ksx * 32);
#pragma unroll
            for (int mt = 0; mt < 2; mt++)
#pragma unroll
                for (int q = 0; q < 4; q++) {
                    mma16816(acc[mt][q * 2 + 0], af[mt], bf_[q][0], bf_[q][1]);
                    mma16816(acc[mt][q * 2 + 1], af[mt], bf_[q][2], bf_[q][3]);
                }
        }
    }

    // ---- write partial sums ----
    {
        float* part = &g_partial[ks][b0 * Ndim];
        const int rb = wm * 32 + (lane >> 2);
        const int cb = wn * 64 + (lane & 3) * 2;
#pragma unroll
        for (int mt = 0; mt < 2; mt++)
#pragma unroll
            for (int nt = 0; nt < 8; nt++) {
                int rr = rb + mt * 16, cc = cb + nt * 8;
                *(float2*)&part[rr * Ndim + cc] =
                    make_float2(acc[mt][nt][0], acc[mt][nt][1]);
                *(float2*)&part[(rr + 8) * Ndim + cc] =
                    make_float2(acc[mt][nt][2], acc[mt][nt][3]);
            }
    }

    // ---- last CTA of this m-tile finalizes ----
    __threadfence();
    __syncthreads();
    if (tid == 0)
        s_last = (atomicAdd(&g_cnt[mtile], 1) == KSPLIT - 1);
    __syncthreads();

    if (s_last) {
        if (tid == 0) g_cnt[mtile] = 0;     // self-reset for graph replay
#pragma unroll
        for (int h = 0; h < 16; h++) {
            int o = b0 * Ndim + h * 1024 + tid * 4;
            float4 s0 = *(const float4*)&g_partial[0][o];
            float4 s1 = *(const float4*)&g_partial[1][o];
            float4 s2 = *(const float4*)&g_partial[2][o];
            float4 s3 = *(const float4*)&g_partial[3][o];
            float4 v;
            v.x = __fdividef(-1.0f, ((s0.x + s1.x) + (s2.x + s3.x)) - 1.0f);
            v.y = __fdividef(-1.0f, ((s0.y + s1.y) + (s2.y + s3.y)) - 1.0f);
            v.z = __fdividef(-1.0f, ((s0.z + s1.z) + (s2.z + s3.z)) - 1.0f);
            v.w = __fdividef(-1.0f, ((s0.w + s1.w) + (s2.w + s3.w)) - 1.0f);
            *(float4*)&out[o] = v;
        }
    }
}

extern "C" void kernel_launch(void* const* d_in, const int* in_sizes, int n_in,
                              void* d_out, int out_size) {
    const float* x = (const float*)d_in[0];   // (4096, 512)
    const float* W = (const float*)d_in[1];   // (128, 512)
    float* out = (float*)d_out;               // (4096, 128)
    (void)in_sizes; (void)n_in; (void)out_size;

    prep_w<<<8 * NKC, 256>>>(W);                        // 128 CTAs
    conj_mma<<<NMT * KSPLIT, 256>>>(x, out);            // 128 CTAs
}